// round 2
// baseline (speedup 1.0000x reference)
#include <cuda_runtime.h>

#define SEQ   4096
#define BATCH 64
#define INP   64
#define HID   256
#define G3    768      // 3*HID
#define NCTA  128      // persistent scan CTAs (<= 148 SMs -> co-resident)

// Scratch (static device allocations are the sanctioned workaround)
__device__ float d_xg[(size_t)SEQ * G3 * BATCH];   // [s][g][b]
__device__ float d_hs[(size_t)SEQ * HID * BATCH];  // [s][j][b]
__device__ unsigned int d_arrive;

__global__ void reset_kernel() { d_arrive = 0u; }

__device__ __forceinline__ void fma2(unsigned long long& acc,
                                     unsigned long long a,
                                     unsigned long long b) {
    asm("fma.rn.f32x2 %0, %1, %2, %0;" : "+l"(acc) : "l"(a), "l"(b));
}

// ---------------------------------------------------------------------------
// Kernel A: xg[s][g][b] = sum_i x[s][b][i] * w_ih[g][i] + b_ih[g]
// ---------------------------------------------------------------------------
__global__ void __launch_bounds__(256) xg_kernel(const float* __restrict__ x,
                                                 const float* __restrict__ w_ih,
                                                 const float* __restrict__ b_ih) {
    __shared__ float xs[INP][BATCH + 1];
    __shared__ float ws[64][INP];
    const int s   = blockIdx.x;
    const int g0  = blockIdx.y * 64;
    const int tid = threadIdx.x;

    const float* xsrc = x + (size_t)s * BATCH * INP;
    for (int idx = tid; idx < BATCH * INP; idx += 256) {
        int b = idx >> 6, i = idx & 63;
        xs[i][b] = xsrc[idx];
    }
    const float* wsrc = w_ih + (size_t)g0 * INP;
    for (int idx = tid; idx < 64 * INP; idx += 256)
        ws[idx >> 6][idx & 63] = wsrc[idx];
    __syncthreads();

    const int b  = tid & 63;
    const int gg = tid >> 6;
    float xr[INP];
#pragma unroll
    for (int i = 0; i < INP; i++) xr[i] = xs[i][b];

    float acc[16];
#pragma unroll
    for (int u = 0; u < 16; u++) acc[u] = 0.0f;
    const int gb = gg * 16;
#pragma unroll
    for (int i4 = 0; i4 < INP / 4; i4++) {
#pragma unroll
        for (int u = 0; u < 16; u++) {
            float4 w4 = *(const float4*)&ws[gb + u][i4 * 4];
            acc[u] += w4.x * xr[i4 * 4 + 0];
            acc[u] += w4.y * xr[i4 * 4 + 1];
            acc[u] += w4.z * xr[i4 * 4 + 2];
            acc[u] += w4.w * xr[i4 * 4 + 3];
        }
    }
    float* dst = d_xg + ((size_t)s * G3 + g0) * BATCH;
#pragma unroll
    for (int u = 0; u < 16; u++) {
        int gl = gb + u;
        dst[(size_t)gl * BATCH + b] = acc[u] + b_ih[g0 + gl];
    }
}

// ---------------------------------------------------------------------------
// Kernel B: persistent GRU scan. 128 CTAs x 128 threads.
// CTA c owns hidden units j0=2c, j0+1 (6 gate rows in smem, duplicated f32x2).
// Sync: one release-reduction per CTA per step; one acquiring poller per CTA.
// MACs: packed fma.rn.f32x2 (2 batch lanes per instruction).
// ---------------------------------------------------------------------------
__global__ void __launch_bounds__(128) scan_kernel(const float* __restrict__ w_hh,
                                                   const float* __restrict__ b_hh) {
    __shared__ __align__(16) float2 ws2[6][HID];   // {w,w} duplicated pairs
    __shared__ float red[8][6][BATCH];             // [ksplit][row][b]
    const int c   = blockIdx.x;
    const int j0  = c * 2;
    const int tid = threadIdx.x;

    for (int idx = tid; idx < 6 * HID; idx += 128) {
        int r  = idx >> 8;
        int k  = idx & 255;
        int jj = r / 3, gam = r % 3;
        float w = w_hh[((size_t)gam * HID + j0 + jj) * HID + k];
        ws2[r][k] = make_float2(w, w);
    }

    const int pb  = tid & 63;              // pointwise: batch
    const int pjj = tid >> 6;              // pointwise: local j (0/1)
    const int pj  = j0 + pjj;
    const float bh_r = b_hh[pj];
    const float bh_z = b_hh[HID + pj];
    const float bh_n = b_hh[2 * HID + pj];

    const int bq    = tid & 15;            // batch quad: b = bq*4 .. bq*4+3
    const int ks    = tid >> 4;            // k-split 0..7 (32 k each)
    const int kbase = ks * 32;

    unsigned int* arr = &d_arrive;
    float h_prev = 0.0f;                   // own (pj,pb) state, register-resident

    __syncthreads();

    for (int t = 0; t < SEQ; t++) {
        // Prefetch this step's input-side gates (independent of the flag).
        const size_t xoff = (size_t)t * G3 * BATCH;
        const float xrv = d_xg[xoff + (size_t)pj * BATCH + pb];
        const float xzv = d_xg[xoff + (size_t)(HID + pj) * BATCH + pb];
        const float xnv = d_xg[xoff + (size_t)(2 * HID + pj) * BATCH + pb];

        unsigned long long acc[6][2];
#pragma unroll
        for (int r = 0; r < 6; r++) { acc[r][0] = 0ull; acc[r][1] = 0ull; }

        if (t > 0) {
            if (tid == 0) {                // single acquiring poller per CTA
                const unsigned int target = (unsigned int)t * NCTA;
                unsigned int v;
                do {
                    asm volatile("ld.acquire.gpu.u32 %0, [%1];"
                                 : "=r"(v) : "l"(arr) : "memory");
                } while (v < target);
            }
            __syncthreads();

            const float* hp = d_hs + (size_t)(t - 1) * HID * BATCH;
#pragma unroll
            for (int kk = 0; kk < 8; kk++) {
                const int k = kbase + kk * 4;
                ulonglong2 H0 = *(const ulonglong2*)&hp[(k + 0) * BATCH + bq * 4];
                ulonglong2 H1 = *(const ulonglong2*)&hp[(k + 1) * BATCH + bq * 4];
                ulonglong2 H2 = *(const ulonglong2*)&hp[(k + 2) * BATCH + bq * 4];
                ulonglong2 H3 = *(const ulonglong2*)&hp[(k + 3) * BATCH + bq * 4];
#pragma unroll
                for (int r = 0; r < 6; r++) {
                    ulonglong2 W01 = *(const ulonglong2*)&ws2[r][k];
                    ulonglong2 W23 = *(const ulonglong2*)&ws2[r][k + 2];
                    fma2(acc[r][0], W01.x, H0.x); fma2(acc[r][1], W01.x, H0.y);
                    fma2(acc[r][0], W01.y, H1.x); fma2(acc[r][1], W01.y, H1.y);
                    fma2(acc[r][0], W23.x, H2.x); fma2(acc[r][1], W23.x, H2.y);
                    fma2(acc[r][0], W23.y, H3.x); fma2(acc[r][1], W23.y, H3.y);
                }
            }
        }
#pragma unroll
        for (int r = 0; r < 6; r++) {
            float2 a0 = *(float2*)&acc[r][0];
            float2 a1 = *(float2*)&acc[r][1];
            red[ks][r][bq * 4 + 0] = a0.x;
            red[ks][r][bq * 4 + 1] = a0.y;
            red[ks][r][bq * 4 + 2] = a1.x;
            red[ks][r][bq * 4 + 3] = a1.y;
        }
        __syncthreads();

        // pointwise GRU update (torch form: n = tanh(xn + r*(hn + bhh_n)))
        float sr = 0.0f, sz = 0.0f, sn = 0.0f;
#pragma unroll
        for (int q = 0; q < 8; q++) {
            sr += red[q][pjj * 3 + 0][pb];
            sz += red[q][pjj * 3 + 1][pb];
            sn += red[q][pjj * 3 + 2][pb];
        }
        const float rg = 1.0f / (1.0f + __expf(-(xrv + sr + bh_r)));
        const float zg = 1.0f / (1.0f + __expf(-(xzv + sz + bh_z)));
        const float ng = tanhf(xnv + rg * (sn + bh_n));
        const float hnew = (1.0f - zg) * ng + zg * h_prev;
        h_prev = hnew;
        d_hs[((size_t)t * HID + pj) * BATCH + pb] = hnew;

        __syncthreads();                   // all stores in this CTA are done
        if (tid == 0)                      // publish once, release semantics
            asm volatile("red.release.gpu.add.u32 [%0], %1;"
                         :: "l"(arr), "r"(1u) : "memory");
    }
}

// ---------------------------------------------------------------------------
// Kernel C: out[s][b] = sum_j fc_w[j] * hs[s][j][b] + fc_b
// ---------------------------------------------------------------------------
__global__ void __launch_bounds__(256) fc_kernel(const float* __restrict__ fc_w,
                                                 const float* __restrict__ fc_b,
                                                 float* __restrict__ out) {
    __shared__ float wsh[HID];
    __shared__ float red[4][BATCH];
    const int s   = blockIdx.x;
    const int tid = threadIdx.x;
    if (tid < HID) wsh[tid] = fc_w[tid];
    __syncthreads();
    const int b  = tid & 63;
    const int jc = tid >> 6;
    const float* hp = d_hs + (size_t)s * HID * BATCH;
    float sum = 0.0f;
#pragma unroll 8
    for (int j = jc * 64; j < jc * 64 + 64; j++)
        sum += wsh[j] * hp[(size_t)j * BATCH + b];
    red[jc][b] = sum;
    __syncthreads();
    if (tid < BATCH)
        out[(size_t)s * BATCH + tid] =
            red[0][tid] + red[1][tid] + red[2][tid] + red[3][tid] + fc_b[0];
}

extern "C" void kernel_launch(void* const* d_in, const int* in_sizes, int n_in,
                              void* d_out, int out_size) {
    const float* x    = (const float*)d_in[0];
    const float* w_ih = (const float*)d_in[1];
    const float* w_hh = (const float*)d_in[2];
    const float* b_ih = (const float*)d_in[3];
    const float* b_hh = (const float*)d_in[4];
    const float* fc_w = (const float*)d_in[5];
    const float* fc_b = (const float*)d_in[6];
    float* out = (float*)d_out;

    reset_kernel<<<1, 1>>>();                       // re-arm barrier each replay
    dim3 ga(SEQ, G3 / 64);
    xg_kernel<<<ga, 256>>>(x, w_ih, b_ih);          // input-side gate projections
    scan_kernel<<<NCTA, 128>>>(w_hh, b_hh);         // persistent sequential scan
    fc_kernel<<<SEQ, 256>>>(fc_w, fc_b, out);       // output head
}

// round 3
// speedup vs baseline: 1.4421x; 1.4421x over previous
#include <cuda_runtime.h>

#define SEQ   4096
#define BATCH 64
#define INP   64
#define HID   256
#define G3    768      // 3*HID
#define NCTA  128      // persistent scan CTAs (<= 148 SMs -> co-resident)

// Scratch (static device allocations are the sanctioned workaround)
__device__ float d_xg[(size_t)SEQ * G3 * BATCH];   // [s][g][b]
__device__ float d_hs[(size_t)SEQ * HID * BATCH];  // [s][j][b]
__device__ unsigned int d_tag[NCTA * 8];           // 32B-strided monotonic epochs

__device__ __forceinline__ void fma2(unsigned long long& acc,
                                     unsigned long long a,
                                     unsigned long long b) {
    asm("fma.rn.f32x2 %0, %1, %2, %0;" : "+l"(acc) : "l"(a), "l"(b));
}

// ---------------------------------------------------------------------------
// Kernel A: xg[s][g][b] = sum_i x[s][b][i] * w_ih[g][i] + b_ih[g]
// ---------------------------------------------------------------------------
__global__ void __launch_bounds__(256) xg_kernel(const float* __restrict__ x,
                                                 const float* __restrict__ w_ih,
                                                 const float* __restrict__ b_ih) {
    __shared__ float xs[INP][BATCH + 1];
    __shared__ float ws[64][INP];
    const int s   = blockIdx.x;
    const int g0  = blockIdx.y * 64;
    const int tid = threadIdx.x;

    const float* xsrc = x + (size_t)s * BATCH * INP;
    for (int idx = tid; idx < BATCH * INP; idx += 256) {
        int b = idx >> 6, i = idx & 63;
        xs[i][b] = xsrc[idx];
    }
    const float* wsrc = w_ih + (size_t)g0 * INP;
    for (int idx = tid; idx < 64 * INP; idx += 256)
        ws[idx >> 6][idx & 63] = wsrc[idx];
    __syncthreads();

    const int b  = tid & 63;
    const int gg = tid >> 6;
    float xr[INP];
#pragma unroll
    for (int i = 0; i < INP; i++) xr[i] = xs[i][b];

    float acc[16];
#pragma unroll
    for (int u = 0; u < 16; u++) acc[u] = 0.0f;
    const int gb = gg * 16;
#pragma unroll
    for (int i4 = 0; i4 < INP / 4; i4++) {
#pragma unroll
        for (int u = 0; u < 16; u++) {
            float4 w4 = *(const float4*)&ws[gb + u][i4 * 4];
            acc[u] += w4.x * xr[i4 * 4 + 0];
            acc[u] += w4.y * xr[i4 * 4 + 1];
            acc[u] += w4.z * xr[i4 * 4 + 2];
            acc[u] += w4.w * xr[i4 * 4 + 3];
        }
    }
    float* dst = d_xg + ((size_t)s * G3 + g0) * BATCH;
#pragma unroll
    for (int u = 0; u < 16; u++) {
        int gl = gb + u;
        __stcs(&dst[(size_t)gl * BATCH + b], acc[u] + b_ih[g0 + gl]);  // streaming: read-once
    }
}

// ---------------------------------------------------------------------------
// Kernel B: persistent GRU scan, dataflow-tag sync (no global barrier).
// 128 CTAs x 128 threads. CTA c owns hidden units j0=2c, j0+1.
// Producer: STG h slice -> bar -> st.release tag[c]=t+1.
// Consumer: warp lane l polls tag of producer (warp*32+l) relaxed, __all_sync,
// one acquire fence, then bulk loads + packed f32x2 MACs.
// ---------------------------------------------------------------------------
__global__ void __launch_bounds__(128) scan_kernel(const float* __restrict__ w_hh,
                                                   const float* __restrict__ b_hh) {
    __shared__ __align__(16) float2 ws2[6][HID];   // {w,w} duplicated pairs
    __shared__ float red[8][6][BATCH];             // [ksplit][row][b]
    const int c   = blockIdx.x;
    const int j0  = c * 2;
    const int tid = threadIdx.x;

    for (int idx = tid; idx < 6 * HID; idx += 128) {
        int r  = idx >> 8;
        int k  = idx & 255;
        int jj = r / 3, gam = r % 3;
        float w = w_hh[((size_t)gam * HID + j0 + jj) * HID + k];
        ws2[r][k] = make_float2(w, w);
    }

    const int pb  = tid & 63;              // pointwise: batch
    const int pjj = tid >> 6;              // pointwise: local j (0/1)
    const int pj  = j0 + pjj;
    const float bh_r = b_hh[pj];
    const float bh_z = b_hh[HID + pj];
    const float bh_n = b_hh[2 * HID + pj];

    const int bq    = tid & 15;            // batch quad: b = bq*4 .. bq*4+3
    const int ks    = tid >> 4;            // k-split 0..7 (32 k each)
    const int kbase = ks * 32;

    // warp w lane l watches producer 32w+l (covers k-range of both ks halves)
    unsigned int* mytag = &d_tag[(((tid >> 5) << 5) + (tid & 31)) * 8];

    float h_prev = 0.0f;                   // own (pj,pb) state, register-resident
    __syncthreads();

    for (int t = 0; t < SEQ; t++) {
        // Prefetch this step's input-side gates (independent of tags).
        const size_t xoff = (size_t)t * G3 * BATCH;
        const float xrv = __ldcs(&d_xg[xoff + (size_t)pj * BATCH + pb]);
        const float xzv = __ldcs(&d_xg[xoff + (size_t)(HID + pj) * BATCH + pb]);
        const float xnv = __ldcs(&d_xg[xoff + (size_t)(2 * HID + pj) * BATCH + pb]);

        unsigned long long acc[6][2];
#pragma unroll
        for (int r = 0; r < 6; r++) { acc[r][0] = 0ull; acc[r][1] = 0ull; }

        if (t > 0) {
            // warp-cooperative discovery of this warp's 32 producers
            const unsigned int tt = (unsigned int)t;
            bool alldone;
            do {
                unsigned int v;
                asm volatile("ld.relaxed.gpu.global.u32 %0, [%1];"
                             : "=r"(v) : "l"(mytag) : "memory");
                alldone = __all_sync(0xFFFFFFFFu, v >= tt);
            } while (!alldone);
            asm volatile("fence.acq_rel.gpu;" ::: "memory");

            const float* hp = d_hs + (size_t)(t - 1) * HID * BATCH;
#pragma unroll
            for (int kk2 = 0; kk2 < 8; kk2++) {
                const int k = kbase + (((kk2 + c) & 7) << 2);   // CTA-rotated order
                ulonglong2 H0 = *(const ulonglong2*)&hp[(k + 0) * BATCH + bq * 4];
                ulonglong2 H1 = *(const ulonglong2*)&hp[(k + 1) * BATCH + bq * 4];
                ulonglong2 H2 = *(const ulonglong2*)&hp[(k + 2) * BATCH + bq * 4];
                ulonglong2 H3 = *(const ulonglong2*)&hp[(k + 3) * BATCH + bq * 4];
#pragma unroll
                for (int r = 0; r < 6; r++) {
                    ulonglong2 W01 = *(const ulonglong2*)&ws2[r][k];
                    ulonglong2 W23 = *(const ulonglong2*)&ws2[r][k + 2];
                    fma2(acc[r][0], W01.x, H0.x); fma2(acc[r][1], W01.x, H0.y);
                    fma2(acc[r][0], W01.y, H1.x); fma2(acc[r][1], W01.y, H1.y);
                    fma2(acc[r][0], W23.x, H2.x); fma2(acc[r][1], W23.x, H2.y);
                    fma2(acc[r][0], W23.y, H3.x); fma2(acc[r][1], W23.y, H3.y);
                }
            }
        }
#pragma unroll
        for (int r = 0; r < 6; r++) {
            float2 a0 = *(float2*)&acc[r][0];
            float2 a1 = *(float2*)&acc[r][1];
            red[ks][r][bq * 4 + 0] = a0.x;
            red[ks][r][bq * 4 + 1] = a0.y;
            red[ks][r][bq * 4 + 2] = a1.x;
            red[ks][r][bq * 4 + 3] = a1.y;
        }
        __syncthreads();

        // pointwise GRU update (torch form: n = tanh(xn + r*(hn + bhh_n)))
        float sr = 0.0f, sz = 0.0f, sn = 0.0f;
#pragma unroll
        for (int q = 0; q < 8; q++) {
            sr += red[q][pjj * 3 + 0][pb];
            sz += red[q][pjj * 3 + 1][pb];
            sn += red[q][pjj * 3 + 2][pb];
        }
        const float rg = 1.0f / (1.0f + __expf(-(xrv + sr + bh_r)));
        const float zg = 1.0f / (1.0f + __expf(-(xzv + sz + bh_z)));
        const float ng = tanhf(xnv + rg * (sn + bh_n));
        const float hnew = (1.0f - zg) * ng + zg * h_prev;
        h_prev = hnew;
        d_hs[((size_t)t * HID + pj) * BATCH + pb] = hnew;

        __syncthreads();                   // CTA's h slice fully stored
        if (tid == 0)                      // publish epoch with release semantics
            asm volatile("st.release.gpu.global.u32 [%0], %1;"
                         :: "l"(&d_tag[c * 8]), "r"((unsigned)(t + 1)) : "memory");
    }
}

// ---------------------------------------------------------------------------
// Kernel C: out[s][b] = sum_j fc_w[j] * hs[s][j][b] + fc_b
// Also re-arms the tag array for the next graph replay.
// ---------------------------------------------------------------------------
__global__ void __launch_bounds__(256) fc_kernel(const float* __restrict__ fc_w,
                                                 const float* __restrict__ fc_b,
                                                 float* __restrict__ out) {
    __shared__ float wsh[HID];
    __shared__ float red[4][BATCH];
    const int s   = blockIdx.x;
    const int tid = threadIdx.x;
    if (s == 0 && tid < NCTA) d_tag[tid * 8] = 0u;   // re-arm for next replay
    if (tid < HID) wsh[tid] = fc_w[tid];
    __syncthreads();
    const int b  = tid & 63;
    const int jc = tid >> 6;
    const float* hp = d_hs + (size_t)s * HID * BATCH;
    float sum = 0.0f;
#pragma unroll 8
    for (int j = jc * 64; j < jc * 64 + 64; j++)
        sum += wsh[j] * __ldcs(&hp[(size_t)j * BATCH + b]);
    red[jc][b] = sum;
    __syncthreads();
    if (tid < BATCH)
        out[(size_t)s * BATCH + tid] =
            red[0][tid] + red[1][tid] + red[2][tid] + red[3][tid] + fc_b[0];
}

extern "C" void kernel_launch(void* const* d_in, const int* in_sizes, int n_in,
                              void* d_out, int out_size) {
    const float* x    = (const float*)d_in[0];
    const float* w_ih = (const float*)d_in[1];
    const float* w_hh = (const float*)d_in[2];
    const float* b_ih = (const float*)d_in[3];
    const float* b_hh = (const float*)d_in[4];
    const float* fc_w = (const float*)d_in[5];
    const float* fc_b = (const float*)d_in[6];
    float* out = (float*)d_out;

    dim3 ga(SEQ, G3 / 64);
    xg_kernel<<<ga, 256>>>(x, w_ih, b_ih);          // input-side gate projections
    scan_kernel<<<NCTA, 128>>>(w_hh, b_hh);         // persistent dataflow scan
    fc_kernel<<<SEQ, 256>>>(fc_w, fc_b, out);       // output head + tag re-arm
}